// round 10
// baseline (speedup 1.0000x reference)
#include <cuda_runtime.h>
#include <cuda_bf16.h>
#include <cstdint>

#define NN 20000
#define EE 500000
#define KK 48

// ---------------- device scratch (no allocations allowed) ----------------
struct __align__(16) ERec { float b[8]; unsigned kx[2]; int src; int pad; };  // 48B

__device__ __align__(16) float    g_basis [EE * 8];
__device__ __align__(16) unsigned char g_kidx [EE * 8];
__device__ __align__(16) ERec     g_rec   [EE];          // dst-sorted edge records
__device__ __align__(16) int      g_cnt   [NN];
__device__ __align__(16) int      g_ofs   [NN + 1];
__device__ __align__(16) int      g_pos   [NN];
// block-split hi/lo bf16 planes: per row, group of 8 values = [8 hi u16][8 lo u16]
__device__ __align__(16) unsigned g_acc2p [NN * KK * 32];
__device__ __align__(16) unsigned g_acc3p [(size_t)NN * KK * 64];
__device__ __align__(16) float    g_h1    [NN * 32];
__device__ __align__(16) float    g_h2    [NN * 64];
__device__ __align__(16) unsigned g_h1s   [NN * 32];     // block-split of g_h1
__device__ __align__(16) unsigned g_h2s   [NN * 64];     // block-split of g_h2
__device__ __align__(16) unsigned g_Bs2   [64  * (1536 + 32)];   // block-split B^T
__device__ __align__(16) unsigned g_Bs3   [128 * (3072 + 64)];

// ---------------- helpers ----------------
__device__ __forceinline__ uint32_t smem_u32(const void* p) {
    uint32_t a;
    asm("{ .reg .u64 t; cvta.to.shared.u64 t, %1; cvt.u32.u64 %0, t; }" : "=r"(a) : "l"(p));
    return a;
}
__device__ __forceinline__ unsigned short bfh(float v) {
    __nv_bfloat16 h = __float2bfloat16(v);
    union { __nv_bfloat16 b; unsigned short u; } c; c.b = h; return c.u;
}
__device__ __forceinline__ float bfhf(float v) {   // value of hi part
    return __bfloat162float(__float2bfloat16(v));
}
__device__ __forceinline__ void split8(const float* v, uint4& hb, uint4& lb) {
    unsigned h[4], l[4];
#pragma unroll
    for (int i = 0; i < 4; i++) {
        float a = v[i * 2], b = v[i * 2 + 1];
        h[i] = (unsigned)bfh(a) | ((unsigned)bfh(b) << 16);
        l[i] = (unsigned)bfh(a - bfhf(a)) | ((unsigned)bfh(b - bfhf(b)) << 16);
    }
    hb = make_uint4(h[0], h[1], h[2], h[3]);
    lb = make_uint4(l[0], l[1], l[2], l[3]);
}
__device__ __forceinline__ void mma16816(float* c, const unsigned* a, unsigned b0, unsigned b1) {
    asm volatile("mma.sync.aligned.m16n8k16.row.col.f32.bf16.bf16.f32 "
        "{%0,%1,%2,%3}, {%4,%5,%6,%7}, {%8,%9}, {%0,%1,%2,%3};"
        : "+f"(c[0]), "+f"(c[1]), "+f"(c[2]), "+f"(c[3])
        : "r"(a[0]), "r"(a[1]), "r"(a[2]), "r"(a[3]), "r"(b0), "r"(b1));
}
__device__ __forceinline__ void ldsm4(unsigned* r, uint32_t addr) {
    asm volatile("ldmatrix.sync.aligned.m8n8.x4.shared.b16 {%0,%1,%2,%3}, [%4];"
        : "=r"(r[0]), "=r"(r[1]), "=r"(r[2]), "=r"(r[3]) : "r"(addr));
}
__device__ __forceinline__ void cpa16(uint32_t dst, const void* src, int sz) {
    asm volatile("cp.async.cg.shared.global [%0], [%1], 16, %2;" :: "r"(dst), "l"(src), "r"(sz));
}
__device__ __forceinline__ void cpa16f(uint32_t dst, const void* src) {
    asm volatile("cp.async.cg.shared.global [%0], [%1], 16;" :: "r"(dst), "l"(src));
}

// ---------------- basis/kidx precompute + cnt zero ----------------
__global__ void precompute_kernel(const float* __restrict__ pseudo, int E) {
    int e = blockIdx.x * blockDim.x + threadIdx.x;
    if (e >= E) return;
    if (e < NN) g_cnt[e] = 0;
    float fr[3]; int lo[3];
    const int ksm1[3] = {2, 7, 1};
#pragma unroll
    for (int d = 0; d < 3; d++) {
        float u = pseudo[e * 3 + d] * (1.0f / 4.5f);
        u = fminf(fmaxf(u, 0.0f), 1.0f);
        float pos = u * (float)ksm1[d];
        float fl = floorf(pos);
        fr[d] = pos - fl;
        lo[d] = (int)fl;
    }
    float b[8]; unsigned char kx[8];
#pragma unroll
    for (int s = 0; s < 8; s++) {
        float w = 1.0f; int idx[3];
#pragma unroll
        for (int d = 0; d < 3; d++) {
            int bit = (s >> d) & 1;
            int id = lo[d] + bit;
            if (id > ksm1[d]) id = ksm1[d];
            idx[d] = id;
            w *= bit ? fr[d] : (1.0f - fr[d]);
        }
        b[s] = w;
        kx[s] = (unsigned char)(idx[0] * 16 + idx[1] * 2 + idx[2]);
    }
    *(float4*)&g_basis[e * 8]     = make_float4(b[0], b[1], b[2], b[3]);
    *(float4*)&g_basis[e * 8 + 4] = make_float4(b[4], b[5], b[6], b[7]);
    uchar4* kp = (uchar4*)&g_kidx[e * 8];
    kp[0] = make_uchar4(kx[0], kx[1], kx[2], kx[3]);
    kp[1] = make_uchar4(kx[4], kx[5], kx[6], kx[7]);
}

__global__ void hist_kernel(const int* __restrict__ ei, int E) {
    int e = blockIdx.x * blockDim.x + threadIdx.x;
    if (e < E) atomicAdd(&g_cnt[ei[E + e]], 1);
}

// fast single-block scan: each thread owns 20 contiguous elements
__global__ void prefix_kernel() {
    constexpr int PER = (NN + 1023) / 1024;   // 20
    __shared__ int ws[32];
    int t = threadIdx.x;
    int base = t * PER;
    int loc[PER]; int sum = 0;
#pragma unroll
    for (int i = 0; i < PER; i++) {
        int idx = base + i;
        int v = (idx < NN) ? g_cnt[idx] : 0;
        loc[i] = sum; sum += v;
    }
    int x = sum;
#pragma unroll
    for (int o = 1; o < 32; o <<= 1) {
        int y = __shfl_up_sync(~0u, x, o);
        if ((t & 31) >= o) x += y;
    }
    if ((t & 31) == 31) ws[t >> 5] = x;
    __syncthreads();
    if (t < 32) {
        int w = ws[t];
#pragma unroll
        for (int o = 1; o < 32; o <<= 1) {
            int y = __shfl_up_sync(~0u, w, o);
            if (t >= o) w += y;
        }
        ws[t] = w;
    }
    __syncthreads();
    int ex = x - sum + ((t >= 32) ? ws[(t >> 5) - 1] : 0);
#pragma unroll
    for (int i = 0; i < PER; i++) {
        int idx = base + i;
        if (idx < NN) { g_ofs[idx] = ex + loc[i]; g_pos[idx] = ex + loc[i]; }
    }
    if (t == 1023) g_ofs[NN] = ex + sum;
}

__global__ void order_kernel(const int* __restrict__ ei, int E) {
    int e = blockIdx.x * blockDim.x + threadIdx.x;
    if (e >= E) return;
    int dst = ei[E + e];
    int p = atomicAdd(&g_pos[dst], 1);
    uint4 q0 = *(const uint4*)&g_basis[e * 8];
    uint4 q1 = *(const uint4*)&g_basis[e * 8 + 4];
    uint2 kv = *(const uint2*)&g_kidx[e * 8];
    uint4 q2 = make_uint4(kv.x, kv.y, (unsigned)ei[e], 0u);
    uint4* rp = (uint4*)&g_rec[p];
    rp[0] = q0; rp[1] = q1; rp[2] = q2;
}

// ---------------- weight transpose + block-split (8-group hi/lo) ----------------
template <int KA, int KH, int NC>
__global__ void bsplit_kernel(const float* __restrict__ W, const float* __restrict__ R) {
    constexpr int KT = KA + KH;
    unsigned* Bs = (KA == 1536) ? g_Bs2 : g_Bs3;
    int i = blockIdx.x * blockDim.x + threadIdx.x;
    if (i >= NC * (KT / 8)) return;
    int n = i / (KT / 8), g = i % (KT / 8);
    float v[8];
#pragma unroll
    for (int j = 0; j < 8; j++) {
        int k = g * 8 + j;
        v[j] = (k < KA) ? W[(size_t)k * NC + n] : R[(size_t)(k - KA) * NC + n];
    }
    uint4 hb, lb; split8(v, hb, lb);
    char* row = (char*)(Bs + (size_t)n * KT);
    *(uint4*)(row + g * 32)      = hb;
    *(uint4*)(row + g * 32 + 16) = lb;
}

// ---------------- fused layer-1: bucket gather + dense + relu + hi/lo split ----------------
// One warp per node (4 nodes per 128-thread CTA). smem 48-entry bucket via shared atomics,
// then h1[n,o] = relu(bucket @ W1 + x[n]*root1 + b1); writes g_h1 (fp32) + g_h1s (split).
__global__ void __launch_bounds__(128) layer1_kernel(const float* __restrict__ x,
                                                     const float* __restrict__ W1,
                                                     const float* __restrict__ root1,
                                                     const float* __restrict__ b1, int N) {
    __shared__ float buck[4][KK];
    __shared__ float hrow[4][32];
    int wi = threadIdx.x >> 5, o = threadIdx.x & 31;
    int n = blockIdx.x * 4 + wi;
    if (n >= N) return;
    float* bk = buck[wi];
#pragma unroll
    for (int k = o; k < KK; k += 32) bk[k] = 0.0f;
    __syncwarp();
    int beg = g_ofs[n], end = g_ofs[n + 1];
    for (int i = beg + o; i < end; i += 32) {
        const uint4* rp = (const uint4*)&g_rec[i];
        uint4 q0 = rp[0], q1 = rp[1], q2 = rp[2];
        float xs = __ldg(&x[(int)q2.z]);
        atomicAdd(&bk[(q2.x      ) & 0xff], __uint_as_float(q0.x) * xs);
        atomicAdd(&bk[(q2.x >>  8) & 0xff], __uint_as_float(q0.y) * xs);
        atomicAdd(&bk[(q2.x >> 16) & 0xff], __uint_as_float(q0.z) * xs);
        atomicAdd(&bk[(q2.x >> 24)       ], __uint_as_float(q0.w) * xs);
        atomicAdd(&bk[(q2.y      ) & 0xff], __uint_as_float(q1.x) * xs);
        atomicAdd(&bk[(q2.y >>  8) & 0xff], __uint_as_float(q1.y) * xs);
        atomicAdd(&bk[(q2.y >> 16) & 0xff], __uint_as_float(q1.z) * xs);
        atomicAdd(&bk[(q2.y >> 24)       ], __uint_as_float(q1.w) * xs);
    }
    __syncwarp();
    float s = x[n] * __ldg(&root1[o]) + __ldg(&b1[o]);
#pragma unroll
    for (int k = 0; k < KK; k++) s += bk[k] * __ldg(&W1[k * 32 + o]);
    s = fmaxf(s, 0.0f);
    g_h1[n * 32 + o] = s;
    hrow[wi][o] = s;
    __syncwarp();
    if (o < 16) {
        float a = hrow[wi][o * 2], b = hrow[wi][o * 2 + 1];
        unsigned hi = (unsigned)bfh(a) | ((unsigned)bfh(b) << 16);
        unsigned lo = (unsigned)bfh(a - bfhf(a)) | ((unsigned)bfh(b - bfhf(b)) << 16);
        char* row = (char*)(g_h1s + (size_t)n * 32);
        int byte = (o >> 2) * 32 + (o & 3) * 4;
        *(unsigned*)(row + byte)      = hi;
        *(unsigned*)(row + byte + 16) = lo;
    }
}

// ---------------- per-node bucket scatter -> block-split output ----------------
template <int CIN>
__global__ void __launch_bounds__(CIN) gather_scatter_kernel(int N) {
    const float* __restrict__ h = (CIN == 32) ? g_h1 : g_h2;
    unsigned* __restrict__ accP = (CIN == 32) ? g_acc2p : g_acc3p;
    __shared__ float buck[KK * CIN];
    int n = blockIdx.x;
    int t = threadIdx.x;
#pragma unroll
    for (int k = 0; k < KK; k++) buck[k * CIN + t] = 0.0f;

    int beg = g_ofs[n], end = g_ofs[n + 1];
    if (beg < end) {
        const uint4* rp = (const uint4*)&g_rec[beg];
        uint4 q0 = rp[0], q1 = rp[1], q2 = rp[2];
        float hv = h[(size_t)(int)q2.z * CIN + t];
        for (int i = beg; i < end; i++) {
            uint4 n0, n1, n2; float hvn = 0.0f;
            if (i + 1 < end) {
                const uint4* np = (const uint4*)&g_rec[i + 1];
                n0 = np[0]; n1 = np[1]; n2 = np[2];
                hvn = h[(size_t)(int)n2.z * CIN + t];
            }
            float bs[8] = {__uint_as_float(q0.x), __uint_as_float(q0.y),
                           __uint_as_float(q0.z), __uint_as_float(q0.w),
                           __uint_as_float(q1.x), __uint_as_float(q1.y),
                           __uint_as_float(q1.z), __uint_as_float(q1.w)};
            unsigned ka = q2.x, kb = q2.y;
            buck[((ka      ) & 0xff) * CIN + t] += bs[0] * hv;
            buck[((ka >>  8) & 0xff) * CIN + t] += bs[1] * hv;
            buck[((ka >> 16) & 0xff) * CIN + t] += bs[2] * hv;
            buck[((ka >> 24)       ) * CIN + t] += bs[3] * hv;
            buck[((kb      ) & 0xff) * CIN + t] += bs[4] * hv;
            buck[((kb >>  8) & 0xff) * CIN + t] += bs[5] * hv;
            buck[((kb >> 16) & 0xff) * CIN + t] += bs[6] * hv;
            buck[((kb >> 24)       ) * CIN + t] += bs[7] * hv;
            q0 = n0; q1 = n1; q2 = n2; hv = hvn;
        }
    }
    __syncthreads();
    char* row = (char*)(accP + (size_t)n * KK * CIN);
    constexpr int NG = KK * CIN / 8;
#pragma unroll
    for (int g = t; g < NG; g += CIN) {
        float v[8];
#pragma unroll
        for (int j = 0; j < 8; j++) v[j] = buck[g * 8 + j];
        uint4 hb, lb; split8(v, hb, lb);
        *(uint4*)(row + g * 32)      = hb;
        *(uint4*)(row + g * 32 + 16) = lb;
    }
}

// ---------------- cp.async bf16-split GEMM: C = relu([A|H] @ B^T + bias) ----------------
// BM=64 rows per CTA, K chunk = 32 values = 128B/row. For the layer-2 instance the
// epilogue additionally writes the block-split copy of h2 (fuses hsplit<64>).
template <int KA, int KH, int BN>
__global__ void __launch_bounds__(256) gemm_cp_kernel(const float* __restrict__ bias,
                                                      float* __restrict__ Cout, int M) {
    constexpr int KT = KA + KH;
    constexpr int CHA = KA / 32, CH = KT / 32;
    constexpr int BM = 64;
    constexpr int ASZ = BM * 128, BSZ = BN * 128, STAGE = ASZ + BSZ;
    constexpr int NTP = BN / 64;
    extern __shared__ __align__(16) char dsm[];
    const uint32_t sb = smem_u32(dsm);

    const unsigned* Ag = (KA == 1536) ? g_acc2p : g_acc3p;
    const unsigned* Hg = (KA == 1536) ? g_h1s : g_h2s;
    const unsigned* Bg = (KA == 1536) ? g_Bs2 : g_Bs3;
    float* C = (KA == 1536) ? g_h2 : Cout;

    const int t = threadIdx.x, wid = t >> 5, lane = t & 31;
    const int wm = wid & 1, wn = wid >> 1;
    const int m0 = blockIdx.x * BM;
    const int lr = lane & 15, lh = lane >> 4;

    auto issue = [&](int c) {
        int buf = c & 1;
        uint32_t sA = sb + buf * STAGE, sB = sA + ASZ;
        const char* gA; size_t strA;
        if (c < CHA) { gA = (const char*)Ag + (size_t)c * 128;        strA = (size_t)KA * 4; }
        else         { gA = (const char*)Hg + (size_t)(c - CHA) * 128; strA = (size_t)KH * 4; }
#pragma unroll
        for (int j = 0; j < 2; j++) {
            int slot = j * 256 + t;
            int r = slot >> 3, s = slot & 7;
            int gr = m0 + r;
            cpa16(sA + r * 128 + ((s ^ (r & 7)) * 16),
                  gA + (size_t)gr * strA + s * 16, (gr < M) ? 16 : 0);
        }
        const char* gB = (const char*)Bg + (size_t)c * 128;
#pragma unroll
        for (int j = 0; j < BN / 32; j++) {
            int slot = j * 256 + t;
            int r = slot >> 3, s = slot & 7;
            cpa16f(sB + r * 128 + ((s ^ (r & 7)) * 16),
                   gB + (size_t)r * ((size_t)KT * 4) + s * 16);
        }
        asm volatile("cp.async.commit_group;" ::: "memory");
    };

    float cacc[2][NTP * 2][4];
#pragma unroll
    for (int i = 0; i < 2; i++)
#pragma unroll
        for (int j = 0; j < NTP * 2; j++)
#pragma unroll
            for (int q = 0; q < 4; q++) cacc[i][j][q] = 0.0f;

    issue(0);
    for (int c = 0; c < CH; c++) {
        if (c + 1 < CH) {
            issue(c + 1);
            asm volatile("cp.async.wait_group 1;" ::: "memory");
        } else {
            asm volatile("cp.async.wait_group 0;" ::: "memory");
        }
        __syncthreads();

        uint32_t sA = sb + (c & 1) * STAGE, sB = sA + ASZ;
#pragma unroll
        for (int ks = 0; ks < 2; ks++) {
            int sg = 4 * ks + 2 * lh;
            unsigned ah[2][4], al[2][4];
#pragma unroll
            for (int mt = 0; mt < 2; mt++) {
                int r = wm * 32 + mt * 16 + lr;
                ldsm4(ah[mt], sA + r * 128 + ((sg ^ (r & 7)) * 16));
                ldsm4(al[mt], sA + r * 128 + (((sg + 1) ^ (r & 7)) * 16));
            }
#pragma unroll
            for (int ntp = 0; ntp < NTP; ntp++) {
                unsigned bh[4], bl[4];
                int rn = wn * (BN / 4) + ntp * 16 + lr;
                ldsm4(bh, sB + rn * 128 + ((sg ^ (rn & 7)) * 16));
                ldsm4(bl, sB + rn * 128 + (((sg + 1) ^ (rn & 7)) * 16));
#pragma unroll
                for (int mt = 0; mt < 2; mt++) {
#pragma unroll
                    for (int ns = 0; ns < 2; ns++) {
                        float* cf = cacc[mt][ntp * 2 + ns];
                        mma16816(cf, ah[mt], bh[ns], bh[ns + 2]);
                        mma16816(cf, ah[mt], bl[ns], bl[ns + 2]);
                        mma16816(cf, al[mt], bh[ns], bh[ns + 2]);
                    }
                }
            }
        }
        __syncthreads();
    }

    auto emit = [&](int row, int col, float vx, float vy) {
        if (row >= M) return;
        float2 o; o.x = vx; o.y = vy;
        *(float2*)(C + (size_t)row * BN + col) = o;
        if constexpr (KA == 1536) {            // also write block-split h2s
            unsigned hi = (unsigned)bfh(vx) | ((unsigned)bfh(vy) << 16);
            unsigned lo = (unsigned)bfh(vx - bfhf(vx)) | ((unsigned)bfh(vy - bfhf(vy)) << 16);
            char* rp = (char*)(g_h2s + (size_t)row * 64);
            int byte = (col >> 3) * 32 + (col & 7) * 2;
            *(unsigned*)(rp + byte)      = hi;
            *(unsigned*)(rp + byte + 16) = lo;
        }
    };
#pragma unroll
    for (int mt = 0; mt < 2; mt++) {
#pragma unroll
        for (int j = 0; j < NTP * 2; j++) {
            int row = m0 + wm * 32 + mt * 16 + (lane >> 2);
            int col = wn * (BN / 4) + (j >> 1) * 16 + (j & 1) * 8 + (lane & 3) * 2;
            float bx = __ldg(&bias[col]), by = __ldg(&bias[col + 1]);
            emit(row, col, fmaxf(cacc[mt][j][0] + bx, 0.0f), fmaxf(cacc[mt][j][1] + by, 0.0f));
            emit(row + 8, col, fmaxf(cacc[mt][j][2] + bx, 0.0f), fmaxf(cacc[mt][j][3] + by, 0.0f));
        }
    }
}

// ---------------- in-place log_softmax over 128 cols ----------------
__global__ void lsm_kernel(float* __restrict__ out) {
    int n = blockIdx.x;
    int t = threadIdx.x;
    float v = out[n * 128 + t];
    float m = v;
#pragma unroll
    for (int o = 16; o > 0; o >>= 1) m = fmaxf(m, __shfl_xor_sync(0xffffffffu, m, o));
    __shared__ float sred[4];
    __shared__ float ssum[4];
    int w = t >> 5, l = t & 31;
    if (l == 0) sred[w] = m;
    __syncthreads();
    float M4 = fmaxf(fmaxf(sred[0], sred[1]), fmaxf(sred[2], sred[3]));
    float e = expf(v - M4);
    float s = e;
#pragma unroll
    for (int o = 16; o > 0; o >>= 1) s += __shfl_xor_sync(0xffffffffu, s, o);
    if (l == 0) ssum[w] = s;
    __syncthreads();
    float S = ssum[0] + ssum[1] + ssum[2] + ssum[3];
    out[n * 128 + t] = v - M4 - logf(S);
}

// ---------------- entry ----------------
extern "C" void kernel_launch(void* const* d_in, const int* in_sizes, int n_in,
                              void* d_out, int out_size) {
    const float* x      = (const float*)d_in[0];
    const int*   ei     = (const int*)  d_in[1];
    const float* pseudo = (const float*)d_in[2];
    const float* W1     = (const float*)d_in[3];
    const float* root1  = (const float*)d_in[4];
    const float* b1     = (const float*)d_in[5];
    const float* W2     = (const float*)d_in[6];
    const float* root2  = (const float*)d_in[7];
    const float* b2     = (const float*)d_in[8];
    const float* W3     = (const float*)d_in[9];
    const float* root3  = (const float*)d_in[10];
    const float* b3     = (const float*)d_in[11];
    float* out = (float*)d_out;
    int N = in_sizes[0];
    int E = in_sizes[1] / 2;

    const int SMEM2 = 2 * (64 * 128 + 64 * 128);    // 32768
    const int SMEM3 = 2 * (64 * 128 + 128 * 128);   // 49152
    cudaFuncSetAttribute(gemm_cp_kernel<1536, 32, 64>,
                         cudaFuncAttributeMaxDynamicSharedMemorySize, SMEM2);
    cudaFuncSetAttribute(gemm_cp_kernel<3072, 64, 128>,
                         cudaFuncAttributeMaxDynamicSharedMemorySize, SMEM3);

    int eb = (E + 255) / 256;
    precompute_kernel<<<eb, 256>>>(pseudo, E);
    hist_kernel<<<eb, 256>>>(ei, E);
    prefix_kernel<<<1, 1024>>>();
    order_kernel<<<eb, 256>>>(ei, E);
    bsplit_kernel<1536, 32, 64><<<(64 * 196 + 255) / 256, 256>>>(W2, root2);
    bsplit_kernel<3072, 64, 128><<<(128 * 392 + 255) / 256, 256>>>(W3, root3);
    layer1_kernel<<<(N + 3) / 4, 128>>>(x, W1, root1, b1, N);
    gather_scatter_kernel<32><<<N, 32>>>(N);
    gemm_cp_kernel<1536, 32, 64><<<(N + 63) / 64, 256, SMEM2>>>(b2, nullptr, N);
    gather_scatter_kernel<64><<<N, 64>>>(N);
    gemm_cp_kernel<3072, 64, 128><<<(N + 63) / 64, 256, SMEM3>>>(b3, out, N);
    lsm_kernel<<<N, 128>>>(out);
}

// round 12
// speedup vs baseline: 1.5521x; 1.5521x over previous
#include <cuda_runtime.h>
#include <cuda_bf16.h>
#include <cstdint>

#define NN 20000
#define EE 500000
#define KK 48

// ---------------- device scratch (no allocations allowed) ----------------
struct __align__(16) ERec { float b[8]; unsigned kx[2]; int src; int pad; };  // 48B

__device__ __align__(16) float    g_basis [EE * 8];
__device__ __align__(16) unsigned char g_kidx [EE * 8];
__device__ __align__(16) ERec     g_rec   [EE];          // dst-sorted edge records
__device__ __align__(16) int      g_cnt   [NN];
__device__ __align__(16) int      g_ofs   [NN + 1];
__device__ __align__(16) int      g_pos   [NN];
// block-split hi/lo bf16 planes: per row, group of 8 values = [8 hi u16][8 lo u16]
__device__ __align__(16) unsigned g_acc2p [NN * KK * 32];
__device__ __align__(16) unsigned g_acc3p [(size_t)NN * KK * 64];
__device__ __align__(16) float    g_h1    [NN * 32];
__device__ __align__(16) float    g_h2    [NN * 64];
__device__ __align__(16) unsigned g_h1s   [NN * 32];     // block-split of g_h1
__device__ __align__(16) unsigned g_h2s   [NN * 64];     // block-split of g_h2
__device__ __align__(16) unsigned g_Bs2   [64  * (1536 + 32)];   // block-split B^T
__device__ __align__(16) unsigned g_Bs3   [128 * (3072 + 64)];

// ---------------- helpers ----------------
__device__ __forceinline__ uint32_t smem_u32(const void* p) {
    uint32_t a;
    asm("{ .reg .u64 t; cvta.to.shared.u64 t, %1; cvt.u32.u64 %0, t; }" : "=r"(a) : "l"(p));
    return a;
}
__device__ __forceinline__ unsigned short bfh(float v) {
    __nv_bfloat16 h = __float2bfloat16(v);
    union { __nv_bfloat16 b; unsigned short u; } c; c.b = h; return c.u;
}
__device__ __forceinline__ float bfhf(float v) {   // value of hi part
    return __bfloat162float(__float2bfloat16(v));
}
__device__ __forceinline__ void split8(const float* v, uint4& hb, uint4& lb) {
    unsigned h[4], l[4];
#pragma unroll
    for (int i = 0; i < 4; i++) {
        float a = v[i * 2], b = v[i * 2 + 1];
        h[i] = (unsigned)bfh(a) | ((unsigned)bfh(b) << 16);
        l[i] = (unsigned)bfh(a - bfhf(a)) | ((unsigned)bfh(b - bfhf(b)) << 16);
    }
    hb = make_uint4(h[0], h[1], h[2], h[3]);
    lb = make_uint4(l[0], l[1], l[2], l[3]);
}
__device__ __forceinline__ void mma16816(float* c, const unsigned* a, unsigned b0, unsigned b1) {
    asm volatile("mma.sync.aligned.m16n8k16.row.col.f32.bf16.bf16.f32 "
        "{%0,%1,%2,%3}, {%4,%5,%6,%7}, {%8,%9}, {%0,%1,%2,%3};"
        : "+f"(c[0]), "+f"(c[1]), "+f"(c[2]), "+f"(c[3])
        : "r"(a[0]), "r"(a[1]), "r"(a[2]), "r"(a[3]), "r"(b0), "r"(b1));
}
__device__ __forceinline__ void ldsm4(unsigned* r, uint32_t addr) {
    asm volatile("ldmatrix.sync.aligned.m8n8.x4.shared.b16 {%0,%1,%2,%3}, [%4];"
        : "=r"(r[0]), "=r"(r[1]), "=r"(r[2]), "=r"(r[3]) : "r"(addr));
}
__device__ __forceinline__ void cpa16(uint32_t dst, const void* src, int sz) {
    asm volatile("cp.async.cg.shared.global [%0], [%1], 16, %2;" :: "r"(dst), "l"(src), "r"(sz));
}
__device__ __forceinline__ void cpa16f(uint32_t dst, const void* src) {
    asm volatile("cp.async.cg.shared.global [%0], [%1], 16;" :: "r"(dst), "l"(src));
}

// ---------------- basis/kidx precompute + cnt zero + dst histogram (fused) ----------------
__global__ void precompute_kernel(const float* __restrict__ pseudo,
                                  const int* __restrict__ ei, int E) {
    int e = blockIdx.x * blockDim.x + threadIdx.x;
    if (e >= E) return;
    if (e < NN) g_cnt[e] = 0;
    float fr[3]; int lo[3];
    const int ksm1[3] = {2, 7, 1};
#pragma unroll
    for (int d = 0; d < 3; d++) {
        float u = pseudo[e * 3 + d] * (1.0f / 4.5f);
        u = fminf(fmaxf(u, 0.0f), 1.0f);
        float pos = u * (float)ksm1[d];
        float fl = floorf(pos);
        fr[d] = pos - fl;
        lo[d] = (int)fl;
    }
    float b[8]; unsigned char kx[8];
#pragma unroll
    for (int s = 0; s < 8; s++) {
        float w = 1.0f; int idx[3];
#pragma unroll
        for (int d = 0; d < 3; d++) {
            int bit = (s >> d) & 1;
            int id = lo[d] + bit;
            if (id > ksm1[d]) id = ksm1[d];
            idx[d] = id;
            w *= bit ? fr[d] : (1.0f - fr[d]);
        }
        b[s] = w;
        kx[s] = (unsigned char)(idx[0] * 16 + idx[1] * 2 + idx[2]);
    }
    *(float4*)&g_basis[e * 8]     = make_float4(b[0], b[1], b[2], b[3]);
    *(float4*)&g_basis[e * 8 + 4] = make_float4(b[4], b[5], b[6], b[7]);
    uchar4* kp = (uchar4*)&g_kidx[e * 8];
    kp[0] = make_uchar4(kx[0], kx[1], kx[2], kx[3]);
    kp[1] = make_uchar4(kx[4], kx[5], kx[6], kx[7]);
}

__global__ void hist_kernel(const int* __restrict__ ei, int E) {
    int e = blockIdx.x * blockDim.x + threadIdx.x;
    if (e < E) atomicAdd(&g_cnt[ei[E + e]], 1);
}

// fast single-block scan: each thread owns 20 contiguous elements
__global__ void prefix_kernel() {
    constexpr int PER = (NN + 1023) / 1024;   // 20
    __shared__ int ws[32];
    int t = threadIdx.x;
    int base = t * PER;
    int loc[PER]; int sum = 0;
#pragma unroll
    for (int i = 0; i < PER; i++) {
        int idx = base + i;
        int v = (idx < NN) ? g_cnt[idx] : 0;
        loc[i] = sum; sum += v;
    }
    int x = sum;
#pragma unroll
    for (int o = 1; o < 32; o <<= 1) {
        int y = __shfl_up_sync(~0u, x, o);
        if ((t & 31) >= o) x += y;
    }
    if ((t & 31) == 31) ws[t >> 5] = x;
    __syncthreads();
    if (t < 32) {
        int w = ws[t];
#pragma unroll
        for (int o = 1; o < 32; o <<= 1) {
            int y = __shfl_up_sync(~0u, w, o);
            if (t >= o) w += y;
        }
        ws[t] = w;
    }
    __syncthreads();
    int ex = x - sum + ((t >= 32) ? ws[(t >> 5) - 1] : 0);
#pragma unroll
    for (int i = 0; i < PER; i++) {
        int idx = base + i;
        if (idx < NN) { g_ofs[idx] = ex + loc[i]; g_pos[idx] = ex + loc[i]; }
    }
    if (t == 1023) g_ofs[NN] = ex + sum;
}

__global__ void order_kernel(const int* __restrict__ ei, int E) {
    int e = blockIdx.x * blockDim.x + threadIdx.x;
    if (e >= E) return;
    int dst = ei[E + e];
    int p = atomicAdd(&g_pos[dst], 1);
    uint4 q0 = *(const uint4*)&g_basis[e * 8];
    uint4 q1 = *(const uint4*)&g_basis[e * 8 + 4];
    uint2 kv = *(const uint2*)&g_kidx[e * 8];
    uint4 q2 = make_uint4(kv.x, kv.y, (unsigned)ei[e], 0u);
    uint4* rp = (uint4*)&g_rec[p];
    rp[0] = q0; rp[1] = q1; rp[2] = q2;
}

// ---------------- weight transpose + block-split (8-group hi/lo) ----------------
template <int KA, int KH, int NC>
__global__ void bsplit_kernel(const float* __restrict__ W, const float* __restrict__ R) {
    constexpr int KT = KA + KH;
    unsigned* Bs = (KA == 1536) ? g_Bs2 : g_Bs3;
    int i = blockIdx.x * blockDim.x + threadIdx.x;
    if (i >= NC * (KT / 8)) return;
    int n = i / (KT / 8), g = i % (KT / 8);
    float v[8];
#pragma unroll
    for (int j = 0; j < 8; j++) {
        int k = g * 8 + j;
        v[j] = (k < KA) ? W[(size_t)k * NC + n] : R[(size_t)(k - KA) * NC + n];
    }
    uint4 hb, lb; split8(v, hb, lb);
    char* row = (char*)(Bs + (size_t)n * KT);
    *(uint4*)(row + g * 32)      = hb;
    *(uint4*)(row + g * 32 + 16) = lb;
}

// ---------------- fused layer-1: bucket gather + dense + relu + hi/lo split ----------------
__global__ void __launch_bounds__(128) layer1_kernel(const float* __restrict__ x,
                                                     const float* __restrict__ W1,
                                                     const float* __restrict__ root1,
                                                     const float* __restrict__ b1, int N) {
    __shared__ float buck[4][KK];
    __shared__ float hrow[4][32];
    int wi = threadIdx.x >> 5, o = threadIdx.x & 31;
    int n = blockIdx.x * 4 + wi;
    if (n >= N) return;
    float* bk = buck[wi];
#pragma unroll
    for (int k = o; k < KK; k += 32) bk[k] = 0.0f;
    __syncwarp();
    int beg = g_ofs[n], end = g_ofs[n + 1];
    for (int i = beg + o; i < end; i += 32) {
        const uint4* rp = (const uint4*)&g_rec[i];
        uint4 q0 = rp[0], q1 = rp[1], q2 = rp[2];
        float xs = __ldg(&x[(int)q2.z]);
        atomicAdd(&bk[(q2.x      ) & 0xff], __uint_as_float(q0.x) * xs);
        atomicAdd(&bk[(q2.x >>  8) & 0xff], __uint_as_float(q0.y) * xs);
        atomicAdd(&bk[(q2.x >> 16) & 0xff], __uint_as_float(q0.z) * xs);
        atomicAdd(&bk[(q2.x >> 24)       ], __uint_as_float(q0.w) * xs);
        atomicAdd(&bk[(q2.y      ) & 0xff], __uint_as_float(q1.x) * xs);
        atomicAdd(&bk[(q2.y >>  8) & 0xff], __uint_as_float(q1.y) * xs);
        atomicAdd(&bk[(q2.y >> 16) & 0xff], __uint_as_float(q1.z) * xs);
        atomicAdd(&bk[(q2.y >> 24)       ], __uint_as_float(q1.w) * xs);
    }
    __syncwarp();
    float s = x[n] * __ldg(&root1[o]) + __ldg(&b1[o]);
#pragma unroll
    for (int k = 0; k < KK; k++) s += bk[k] * __ldg(&W1[k * 32 + o]);
    s = fmaxf(s, 0.0f);
    g_h1[n * 32 + o] = s;
    hrow[wi][o] = s;
    __syncwarp();
    if (o < 16) {
        float a = hrow[wi][o * 2], b = hrow[wi][o * 2 + 1];
        unsigned hi = (unsigned)bfh(a) | ((unsigned)bfh(b) << 16);
        unsigned lo = (unsigned)bfh(a - bfhf(a)) | ((unsigned)bfh(b - bfhf(b)) << 16);
        char* row = (char*)(g_h1s + (size_t)n * 32);
        int byte = (o >> 2) * 32 + (o & 3) * 4;
        *(unsigned*)(row + byte)      = hi;
        *(unsigned*)(row + byte + 16) = lo;
    }
}

// ---------------- per-node bucket scatter -> block-split output ----------------
template <int CIN>
__global__ void __launch_bounds__(CIN) gather_scatter_kernel(int N) {
    const float* __restrict__ h = (CIN == 32) ? g_h1 : g_h2;
    unsigned* __restrict__ accP = (CIN == 32) ? g_acc2p : g_acc3p;
    __shared__ float buck[KK * CIN];
    int n = blockIdx.x;
    int t = threadIdx.x;
#pragma unroll
    for (int k = 0; k < KK; k++) buck[k * CIN + t] = 0.0f;

    int beg = g_ofs[n], end = g_ofs[n + 1];
    if (beg < end) {
        const uint4* rp = (const uint4*)&g_rec[beg];
        uint4 q0 = rp[0], q1 = rp[1], q2 = rp[2];
        float hv = h[(size_t)(int)q2.z * CIN + t];
        for (int i = beg; i < end; i++) {
            uint4 n0, n1, n2; float hvn = 0.0f;
            if (i + 1 < end) {
                const uint4* np = (const uint4*)&g_rec[i + 1];
                n0 = np[0]; n1 = np[1]; n2 = np[2];
                hvn = h[(size_t)(int)n2.z * CIN + t];
            }
            float bs[8] = {__uint_as_float(q0.x), __uint_as_float(q0.y),
                           __uint_as_float(q0.z), __uint_as_float(q0.w),
                           __uint_as_float(q1.x), __uint_as_float(q1.y),
                           __uint_as_float(q1.z), __uint_as_float(q1.w)};
            unsigned ka = q2.x, kb = q2.y;
            buck[((ka      ) & 0xff) * CIN + t] += bs[0] * hv;
            buck[((ka >>  8) & 0xff) * CIN + t] += bs[1] * hv;
            buck[((ka >> 16) & 0xff) * CIN + t] += bs[2] * hv;
            buck[((ka >> 24)       ) * CIN + t] += bs[3] * hv;
            buck[((kb      ) & 0xff) * CIN + t] += bs[4] * hv;
            buck[((kb >>  8) & 0xff) * CIN + t] += bs[5] * hv;
            buck[((kb >> 16) & 0xff) * CIN + t] += bs[6] * hv;
            buck[((kb >> 24)       ) * CIN + t] += bs[7] * hv;
            q0 = n0; q1 = n1; q2 = n2; hv = hvn;
        }
    }
    __syncthreads();
    char* row = (char*)(accP + (size_t)n * KK * CIN);
    constexpr int NG = KK * CIN / 8;
#pragma unroll
    for (int g = t; g < NG; g += CIN) {
        float v[8];
#pragma unroll
        for (int j = 0; j < 8; j++) v[j] = buck[g * 8 + j];
        uint4 hb, lb; split8(v, hb, lb);
        *(uint4*)(row + g * 32)      = hb;
        *(uint4*)(row + g * 32 + 16) = lb;
    }
}

// ---------------- cp.async bf16-split GEMM: C = relu([A|H] @ B^T + bias) ----------------
template <int KA, int KH, int BN>
__global__ void __launch_bounds__(256) gemm_cp_kernel(const float* __restrict__ bias,
                                                      float* __restrict__ Cout, int M) {
    constexpr int KT = KA + KH;
    constexpr int CHA = KA / 32, CH = KT / 32;
    constexpr int BM = 64;
    constexpr int ASZ = BM * 128, BSZ = BN * 128, STAGE = ASZ + BSZ;
    constexpr int NTP = BN / 64;
    extern __shared__ __align__(16) char dsm[];
    const uint32_t sb = smem_u32(dsm);

    const unsigned* Ag = (KA == 1536) ? g_acc2p : g_acc3p;
    const unsigned* Hg = (KA == 1536) ? g_h1s : g_h2s;
    const unsigned* Bg = (KA == 1536) ? g_Bs2 : g_Bs3;
    float* C = (KA == 1536) ? g_h2 : Cout;

    const int t = threadIdx.x, wid = t >> 5, lane = t & 31;
    const int wm = wid & 1, wn = wid >> 1;
    const int m0 = blockIdx.x * BM;
    const int lr = lane & 15, lh = lane >> 4;

    auto issue = [&](int c) {
        int buf = c & 1;
        uint32_t sA = sb + buf * STAGE, sB = sA + ASZ;
        const char* gA; size_t strA;
        if (c < CHA) { gA = (const char*)Ag + (size_t)c * 128;        strA = (size_t)KA * 4; }
        else         { gA = (const char*)Hg + (size_t)(c - CHA) * 128; strA = (size_t)KH * 4; }
#pragma unroll
        for (int j = 0; j < 2; j++) {
            int slot = j * 256 + t;
            int r = slot >> 3, s = slot & 7;
            int gr = m0 + r;
            cpa16(sA + r * 128 + ((s ^ (r & 7)) * 16),
                  gA + (size_t)gr * strA + s * 16, (gr < M) ? 16 : 0);
        }
        const char* gB = (const char*)Bg + (size_t)c * 128;
#pragma unroll
        for (int j = 0; j < BN / 32; j++) {
            int slot = j * 256 + t;
            int r = slot >> 3, s = slot & 7;
            cpa16f(sB + r * 128 + ((s ^ (r & 7)) * 16),
                   gB + (size_t)r * ((size_t)KT * 4) + s * 16);
        }
        asm volatile("cp.async.commit_group;" ::: "memory");
    };

    float cacc[2][NTP * 2][4];
#pragma unroll
    for (int i = 0; i < 2; i++)
#pragma unroll
        for (int j = 0; j < NTP * 2; j++)
#pragma unroll
            for (int q = 0; q < 4; q++) cacc[i][j][q] = 0.0f;

    issue(0);
    for (int c = 0; c < CH; c++) {
        if (c + 1 < CH) {
            issue(c + 1);
            asm volatile("cp.async.wait_group 1;" ::: "memory");
        } else {
            asm volatile("cp.async.wait_group 0;" ::: "memory");
        }
        __syncthreads();

        uint32_t sA = sb + (c & 1) * STAGE, sB = sA + ASZ;
#pragma unroll
        for (int ks = 0; ks < 2; ks++) {
            int sg = 4 * ks + 2 * lh;
            unsigned ah[2][4], al[2][4];
#pragma unroll
            for (int mt = 0; mt < 2; mt++) {
                int r = wm * 32 + mt * 16 + lr;
                ldsm4(ah[mt], sA + r * 128 + ((sg ^ (r & 7)) * 16));
                ldsm4(al[mt], sA + r * 128 + (((sg + 1) ^ (r & 7)) * 16));
            }
#pragma unroll
            for (int ntp = 0; ntp < NTP; ntp++) {
                unsigned bh[4], bl[4];
                int rn = wn * (BN / 4) + ntp * 16 + lr;
                ldsm4(bh, sB + rn * 128 + ((sg ^ (rn & 7)) * 16));
                ldsm4(bl, sB + rn * 128 + (((sg + 1) ^ (rn & 7)) * 16));
#pragma unroll
                for (int mt = 0; mt < 2; mt++) {
#pragma unroll
                    for (int ns = 0; ns < 2; ns++) {
                        float* cf = cacc[mt][ntp * 2 + ns];
                        mma16816(cf, ah[mt], bh[ns], bh[ns + 2]);
                        mma16816(cf, ah[mt], bl[ns], bl[ns + 2]);
                        mma16816(cf, al[mt], bh[ns], bh[ns + 2]);
                    }
                }
            }
        }
        __syncthreads();
    }

    auto emit = [&](int row, int col, float vx, float vy) {
        if (row >= M) return;
        float2 o; o.x = vx; o.y = vy;
        *(float2*)(C + (size_t)row * BN + col) = o;
        if constexpr (KA == 1536) {            // also write block-split h2s
            unsigned hi = (unsigned)bfh(vx) | ((unsigned)bfh(vy) << 16);
            unsigned lo = (unsigned)bfh(vx - bfhf(vx)) | ((unsigned)bfh(vy - bfhf(vy)) << 16);
            char* rp = (char*)(g_h2s + (size_t)row * 64);
            int byte = (col >> 3) * 32 + (col & 7) * 2;
            *(unsigned*)(rp + byte)      = hi;
            *(unsigned*)(rp + byte + 16) = lo;
        }
    };
#pragma unroll
    for (int mt = 0; mt < 2; mt++) {
#pragma unroll
        for (int j = 0; j < NTP * 2; j++) {
            int row = m0 + wm * 32 + mt * 16 + (lane >> 2);
            int col = wn * (BN / 4) + (j >> 1) * 16 + (j & 1) * 8 + (lane & 3) * 2;
            float bx = __ldg(&bias[col]), by = __ldg(&bias[col + 1]);
            emit(row, col, fmaxf(cacc[mt][j][0] + bx, 0.0f), fmaxf(cacc[mt][j][1] + by, 0.0f));
            emit(row + 8, col, fmaxf(cacc[mt][j][2] + bx, 0.0f), fmaxf(cacc[mt][j][3] + by, 0.0f));
        }
    }
}

// ---------------- in-place log_softmax over 128 cols ----------------
__global__ void lsm_kernel(float* __restrict__ out) {
    int n = blockIdx.x;
    int t = threadIdx.x;
    float v = out[n * 128 + t];
    float m = v;
#pragma unroll
    for (int o = 16; o > 0; o >>= 1) m = fmaxf(m, __shfl_xor_sync(0xffffffffu, m, o));
    __shared__ float sred[4];
    __shared__ float ssum[4];
    int w = t >> 5, l = t & 31;
    if (l == 0) sred[w] = m;
    __syncthreads();
    float M4 = fmaxf(fmaxf(sred[0], sred[1]), fmaxf(sred[2], sred[3]));
    float e = expf(v - M4);
    float s = e;
#pragma unroll
    for (int o = 16; o > 0; o >>= 1) s += __shfl_xor_sync(0xffffffffu, s, o);
    if (l == 0) ssum[w] = s;
    __syncthreads();
    float S = ssum[0] + ssum[1] + ssum[2] + ssum[3];
    out[n * 128 + t] = v - M4 - logf(S);
}

// ---------------- entry ----------------
extern "C" void kernel_launch(void* const* d_in, const int* in_sizes, int n_in,
                              void* d_out, int out_size) {
    const float* x      = (const float*)d_in[0];
    const int*   ei     = (const int*)  d_in[1];
    const float* pseudo = (const float*)d_in[2];
    const float* W1     = (const float*)d_in[3];
    const float* root1  = (const float*)d_in[4];
    const float* b1     = (const float*)d_in[5];
    const float* W2     = (const float*)d_in[6];
    const float* root2  = (const float*)d_in[7];
    const float* b2     = (const float*)d_in[8];
    const float* W3     = (const float*)d_in[9];
    const float* root3  = (const float*)d_in[10];
    const float* b3     = (const float*)d_in[11];
    float* out = (float*)d_out;
    int N = in_sizes[0];
    int E = in_sizes[1] / 2;

    const int SMEM2 = 2 * (64 * 128 + 64 * 128);    // 32768
    const int SMEM3 = 2 * (64 * 128 + 128 * 128);   // 49152
    cudaFuncSetAttribute(gemm_cp_kernel<1536, 32, 64>,
                         cudaFuncAttributeMaxDynamicSharedMemorySize, SMEM2);
    cudaFuncSetAttribute(gemm_cp_kernel<3072, 64, 128>,
                         cudaFuncAttributeMaxDynamicSharedMemorySize, SMEM3);

    int eb = (E + 255) / 256;
    precompute_kernel<<<eb, 256>>>(pseudo, ei, E);
    hist_kernel<<<eb, 256>>>(ei, E);
    prefix_kernel<<<1, 1024>>>();
    order_kernel<<<eb, 256>>>(ei, E);
    bsplit_kernel<1536, 32, 64><<<(64 * 196 + 255) / 256, 256>>>(W2, root2);
    bsplit_kernel<3072, 64, 128><<<(128 * 392 + 255) / 256, 256>>>(W3, root3);
    layer1_kernel<<<(N + 3) / 4, 128>>>(x, W1, root1, b1, N);
    gather_scatter_kernel<32><<<N, 32>>>(N);
    gemm_cp_kernel<1536, 32, 64><<<(N + 63) / 64, 256, SMEM2>>>(b2, nullptr, N);
    gather_scatter_kernel<64><<<N, 64>>>(N);
    gemm_cp_kernel<3072, 64, 128><<<(N + 63) / 64, 256, SMEM3>>>(b3, out, N);
    lsm_kernel<<<N, 128>>>(out);
}